// round 6
// baseline (speedup 1.0000x reference)
#include <cuda_runtime.h>
#include <cuda_fp16.h>
#include <stdint.h>

// Fixed problem shape: N=100000 nodes, E=1600000 edges, dims 128 -> 128 -> 40.
#define NMAX 100352
#define EMAX 1600000

// ---------------- device scratch (no allocations allowed) ----------------
__device__ int    g_deg[NMAX];
__device__ __align__(16) int g_rowptr[NMAX + 1];
__device__ int    g_cursor[NMAX];
__device__ unsigned int g_tilestate[128];
__device__ __align__(16) int g_csrsrc[EMAX];
__device__ float  g_dinv[NMAX];
__device__ __align__(16) __half g_ph[(size_t)NMAX * 128];  // fp16 messages
__device__ float  g_hidden_scratch[(size_t)NMAX * 128];    // fallback hidden storage
__device__ int    g_idx64;                                 // 1 if edge_index is int64

// ---------------- packed f32x2 helpers ----------------
__device__ __forceinline__ unsigned long long pack2(float lo, float hi) {
    unsigned long long r;
    asm("mov.b64 %0, {%1, %2};" : "=l"(r) : "f"(lo), "f"(hi));
    return r;
}
__device__ __forceinline__ void unpack2(unsigned long long v, float& lo, float& hi) {
    asm("mov.b64 {%0, %1}, %2;" : "=f"(lo), "=f"(hi) : "l"(v));
}
__device__ __forceinline__ unsigned long long fma2(unsigned long long a,
                                                   unsigned long long b,
                                                   unsigned long long c) {
    unsigned long long d;
    asm("fma.rn.f32x2 %0, %1, %2, %3;" : "=l"(d) : "l"(a), "l"(b), "l"(c));
    return d;
}

// ---------------- zero + dtype detection (one kernel) ----------------
__global__ void k_zero_detect(const int* __restrict__ ei32, int n) {
    int i = blockIdx.x * blockDim.x + threadIdx.x;
    if (i < n) g_deg[i] = 0;
    if (i < 128) g_tilestate[i] = 0;
    if (i == 0) {
        int any = 0;
#pragma unroll
        for (int k = 0; k < 64; ++k) any |= ei32[2 * k + 1];
        g_idx64 = (any == 0) ? 1 : 0;
    }
}

__device__ __forceinline__ int edge_at(const void* ei, long long i) {
    if (g_idx64) return (int)((const long long*)ei)[i];
    return ((const int*)ei)[i];
}

// ---------------- degree count ----------------
__global__ void k_deg_count(const void* __restrict__ ei, int E, int n) {
    int e = blockIdx.x * blockDim.x + threadIdx.x;
    if (e < E) {
        int d = edge_at(ei, (long long)E + e);
        if ((unsigned)d < (unsigned)n) atomicAdd(&g_deg[d], 1);
    }
}

// ---------------- single-pass decoupled-lookback scan + finish ----------------
// 1024 items per tile (256 threads x 4). All (<=98) tiles resident -> spin safe.
// tilestate: bits[0:30) value, bits[30:32) flag (0 invalid, 1 aggregate, 2 prefix).
__global__ void k_scan(int n, int E) {
    __shared__ int ssum[256];
    __shared__ int s_excl;
    int tid = threadIdx.x;
    int tile = blockIdx.x;
    int base = tile * 1024 + tid * 4;
    int v0 = (base + 0 < n) ? g_deg[base + 0] : 0;
    int v1 = (base + 1 < n) ? g_deg[base + 1] : 0;
    int v2 = (base + 2 < n) ? g_deg[base + 2] : 0;
    int v3 = (base + 3 < n) ? g_deg[base + 3] : 0;
    int p0 = 0, p1 = v0, p2 = v0 + v1, p3 = v0 + v1 + v2;
    int total = p3 + v3;
    ssum[tid] = total;
    __syncthreads();
    for (int off = 1; off < 256; off <<= 1) {
        int v = 0;
        if (tid >= off) v = ssum[tid - off];
        __syncthreads();
        if (tid >= off) ssum[tid] += v;
        __syncthreads();
    }
    int excl_in_tile = ssum[tid] - total;
    int tile_total = ssum[255];

    if (tid == 0) {
        if (tile == 0) {
            __threadfence();
            *(volatile unsigned int*)&g_tilestate[0] = (2u << 30) | (unsigned)tile_total;
            s_excl = 0;
        } else {
            *(volatile unsigned int*)&g_tilestate[tile] = (1u << 30) | (unsigned)tile_total;
            __threadfence();
            int excl = 0;
            int t = tile - 1;
            while (true) {
                unsigned int s = *(volatile unsigned int*)&g_tilestate[t];
                unsigned int f = s >> 30;
                if (f == 0) continue;
                excl += (int)(s & 0x3FFFFFFFu);
                if (f == 2) break;
                --t;
            }
            __threadfence();
            *(volatile unsigned int*)&g_tilestate[tile] = (2u << 30) | (unsigned)(excl + tile_total);
            s_excl = excl;
        }
    }
    __syncthreads();
    int excl = s_excl + excl_in_tile;

#pragma unroll
    for (int q = 0; q < 4; ++q) {
        int i = base + q;
        if (i < n) {
            int pv = excl + ((q == 0) ? p0 : (q == 1) ? p1 : (q == 2) ? p2 : p3);
            g_rowptr[i] = pv;
            g_cursor[i] = pv;
            int dv = (q == 0) ? v0 : (q == 1) ? v1 : (q == 2) ? v2 : v3;
            g_dinv[i] = rsqrtf((float)(dv + 1));
        }
    }
    if (tile == 0 && tid == 0) g_rowptr[n] = E;
}

__global__ void k_scatter(const void* __restrict__ ei, int E, int n) {
    int e = blockIdx.x * blockDim.x + threadIdx.x;
    if (e < E) {
        int s = edge_at(ei, e);
        int d = edge_at(ei, (long long)E + e);
        if ((unsigned)d < (unsigned)n && (unsigned)s < (unsigned)n) {
            int pos = atomicAdd(&g_cursor[d], 1);
            if (pos < EMAX) g_csrsrc[pos] = s;
        }
    }
}

// ---------------- GEMM1: g_ph[node, f0:f0+FT] = fp16(X @ W) (unscaled) ----
// ---------------- GEMM2 (SCALED=1): g_ph = fp16(dinv[node] * (X @ W)) ----
template <int FT, int SCALED>
__launch_bounds__(256)
__global__ void k_gemm(const float* __restrict__ X, const float* __restrict__ W,
                       int ldw, int ldp, int n) {
    __shared__ __align__(16) float sW[32 * FT];
    __shared__ __align__(16) float sx[256 * 33];
    const int tid = threadIdx.x;
    const int n0 = blockIdx.x * 256;
    const int f0 = blockIdx.y * FT;
    unsigned long long acc2[FT / 2];
#pragma unroll
    for (int j = 0; j < FT / 2; ++j) acc2[j] = 0ULL;

    for (int kc = 0; kc < 4; ++kc) {
        __syncthreads();
        for (int t = tid; t < 256 * 8; t += 256) {
            int r = t >> 3, c4 = (t & 7) * 4;
            int node = n0 + r;
            float4 xv = make_float4(0.f, 0.f, 0.f, 0.f);
            if (node < n)
                xv = *(const float4*)(X + (size_t)node * 128 + kc * 32 + c4);
            float* d = &sx[r * 33 + c4];
            d[0] = xv.x; d[1] = xv.y; d[2] = xv.z; d[3] = xv.w;
        }
        for (int t = tid; t < 32 * (FT / 4); t += 256) {
            int k = t / (FT / 4), q = t % (FT / 4);
            float4 wv = *(const float4*)(W + (size_t)(kc * 32 + k) * ldw + f0 + q * 4);
            *(float4*)(&sW[k * FT + q * 4]) = wv;
        }
        __syncthreads();
#pragma unroll
        for (int kk = 0; kk < 32; ++kk) {
            float xv = sx[tid * 33 + kk];
            unsigned long long xx = pack2(xv, xv);
            const ulonglong2* wrow = (const ulonglong2*)(&sW[kk * FT]);
#pragma unroll
            for (int j4 = 0; j4 < FT / 4; ++j4) {
                ulonglong2 w = wrow[j4];
                acc2[j4 * 2 + 0] = fma2(xx, w.x, acc2[j4 * 2 + 0]);
                acc2[j4 * 2 + 1] = fma2(xx, w.y, acc2[j4 * 2 + 1]);
            }
        }
    }
    int node = n0 + tid;
    if (node < n) {
        float sc = SCALED ? g_dinv[node] : 1.0f;
        __half2* P = (__half2*)(g_ph + (size_t)node * ldp + f0);
#pragma unroll
        for (int j2 = 0; j2 < FT / 2; ++j2) {
            float2 f;
            unpack2(acc2[j2], f.x, f.y);
            if (SCALED) { f.x *= sc; f.y *= sc; }
            P[j2] = __float22half2_rn(f);
        }
    }
}

// ---------------- scale pass: g_ph[i,:] *= dinv[i] (layer 1, in place) ----
__global__ void k_scale128(int n) {
    long long idx = (long long)blockIdx.x * blockDim.x + threadIdx.x; // one uint2 (4 halves)
    long long tot = (long long)n * 32;
    if (idx >= tot) return;
    int node = (int)(idx >> 5);
    float di = g_dinv[node];
    uint2* p = (uint2*)g_ph;
    uint2 r = p[idx];
    float2 a = __half22float2(*(const __half2*)&r.x);
    float2 b = __half22float2(*(const __half2*)&r.y);
    a.x *= di; a.y *= di; b.x *= di; b.y *= di;
    __half2 ha = __float22half2_rn(a);
    __half2 hb = __float22half2_rn(b);
    r.x = *(const unsigned int*)&ha;
    r.y = *(const unsigned int*)&hb;
    p[idx] = r;
}

// ---------------- aggregation: one warp per node, scaled fp16 messages ----
__device__ __forceinline__ float4 cvt4(uint2 r) {
    float2 a = __half22float2(*(const __half2*)&r.x);
    float2 b = __half22float2(*(const __half2*)&r.y);
    return make_float4(a.x, a.y, b.x, b.y);
}
__device__ __forceinline__ void acc4(float4& acc, float4 v) {
    acc.x += v.x; acc.y += v.y; acc.z += v.z; acc.w += v.w;
}

__global__ void k_agg128(const float* __restrict__ bias, float* __restrict__ out, int n) {
    int warp = (blockIdx.x * blockDim.x + threadIdx.x) >> 5;
    if (warp >= n) return;
    int lane = threadIdx.x & 31;
    const uint2* p = (const uint2*)g_ph;      // 4 halves per uint2; node stride 32
    float diw = g_dinv[warp];
    float4 acc = cvt4(p[(size_t)warp * 32 + lane]);   // self message (already scaled)
    int j = g_rowptr[warp];
    int end = g_rowptr[warp + 1];
    // peel to 16B alignment of csrsrc index
    for (; j < end && (j & 3); ++j)
        acc4(acc, cvt4(__ldg(&p[(size_t)g_csrsrc[j] * 32 + lane])));
    for (; j + 4 <= end; j += 4) {
        int4 s4 = __ldg((const int4*)&g_csrsrc[j]);
        float4 v0 = cvt4(__ldg(&p[(size_t)s4.x * 32 + lane]));
        float4 v1 = cvt4(__ldg(&p[(size_t)s4.y * 32 + lane]));
        float4 v2 = cvt4(__ldg(&p[(size_t)s4.z * 32 + lane]));
        float4 v3 = cvt4(__ldg(&p[(size_t)s4.w * 32 + lane]));
        acc.x += (v0.x + v1.x) + (v2.x + v3.x);
        acc.y += (v0.y + v1.y) + (v2.y + v3.y);
        acc.z += (v0.z + v1.z) + (v2.z + v3.z);
        acc.w += (v0.w + v1.w) + (v2.w + v3.w);
    }
    for (; j < end; ++j)
        acc4(acc, cvt4(__ldg(&p[(size_t)g_csrsrc[j] * 32 + lane])));
    float4 bb = ((const float4*)bias)[lane];
    float4 o;
    o.x = fmaxf(fmaf(acc.x, diw, bb.x), 0.f);
    o.y = fmaxf(fmaf(acc.y, diw, bb.y), 0.f);
    o.z = fmaxf(fmaf(acc.z, diw, bb.z), 0.f);
    o.w = fmaxf(fmaf(acc.w, diw, bb.w), 0.f);
    ((float4*)out)[(size_t)warp * 32 + lane] = o;
}

__global__ void k_agg40(const float* __restrict__ bias, float* __restrict__ out, int n) {
    int warp = (blockIdx.x * blockDim.x + threadIdx.x) >> 5;
    if (warp >= n) return;
    int lane = threadIdx.x & 31;
    bool act = lane < 20;
    const unsigned int* p = (const unsigned int*)g_ph; // 2 halves per uint; node stride 20
    float diw = g_dinv[warp];
    float2 acc = make_float2(0.f, 0.f);
    if (act) {
        float2 self = __half22float2(*(const __half2*)&p[(size_t)warp * 20 + lane]);
        acc = self;                                   // self message (already scaled)
    }
    int j = g_rowptr[warp];
    int end = g_rowptr[warp + 1];
    for (; j < end && (j & 3); ++j) {
        int s = g_csrsrc[j];
        if (act) {
            unsigned int r = __ldg(&p[(size_t)s * 20 + lane]);
            float2 v = __half22float2(*(const __half2*)&r);
            acc.x += v.x; acc.y += v.y;
        }
    }
    for (; j + 4 <= end; j += 4) {
        int4 s4 = __ldg((const int4*)&g_csrsrc[j]);
        if (act) {
            unsigned int r0 = __ldg(&p[(size_t)s4.x * 20 + lane]);
            unsigned int r1 = __ldg(&p[(size_t)s4.y * 20 + lane]);
            unsigned int r2 = __ldg(&p[(size_t)s4.z * 20 + lane]);
            unsigned int r3 = __ldg(&p[(size_t)s4.w * 20 + lane]);
            float2 v0 = __half22float2(*(const __half2*)&r0);
            float2 v1 = __half22float2(*(const __half2*)&r1);
            float2 v2 = __half22float2(*(const __half2*)&r2);
            float2 v3 = __half22float2(*(const __half2*)&r3);
            acc.x += (v0.x + v1.x) + (v2.x + v3.x);
            acc.y += (v0.y + v1.y) + (v2.y + v3.y);
        }
    }
    for (; j < end; ++j) {
        int s = g_csrsrc[j];
        if (act) {
            unsigned int r = __ldg(&p[(size_t)s * 20 + lane]);
            float2 v = __half22float2(*(const __half2*)&r);
            acc.x += v.x; acc.y += v.y;
        }
    }
    if (act) {
        float2 bb = ((const float2*)bias)[lane];
        float2 o;
        o.x = fmaf(acc.x, diw, bb.x);
        o.y = fmaf(acc.y, diw, bb.y);
        ((float2*)out)[(size_t)warp * 20 + lane] = o;
    }
}

// ---------------- launch ----------------
extern "C" void kernel_launch(void* const* d_in, const int* in_sizes, int n_in,
                              void* d_out, int out_size) {
    const float* x  = (const float*)d_in[0];
    const void*  ei = d_in[1];
    const float* W1 = (const float*)d_in[2];
    const float* b1 = (const float*)d_in[3];
    const float* W2 = (const float*)d_in[4];
    const float* b2 = (const float*)d_in[5];

    int n = in_sizes[0] / 128;
    int E = in_sizes[1] / 2;

    float* out    = (float*)d_out;
    float* logits = out;                       // [n, 40]
    float* hidden;
    if ((size_t)out_size >= (size_t)n * (40 + 128)) {
        hidden = out + (size_t)n * 40;         // [n, 128]
    } else {
        cudaGetSymbolAddress((void**)&hidden, g_hidden_scratch);
    }

    int nb_n = (n + 255) / 256;
    int nb_e = (E + 255) / 256;
    int nb_scan = (n + 1023) / 1024;
    int nb_warp = (n + 7) / 8;
    int nb_sc = (int)(((long long)n * 32 + 255) / 256);

    // Fork a side stream for GEMM1 (independent of the CSR chain).
    cudaStream_t s2;
    cudaEvent_t evFork, evGemm;
    cudaStreamCreateWithFlags(&s2, cudaStreamNonBlocking);
    cudaEventCreateWithFlags(&evFork, cudaEventDisableTiming);
    cudaEventCreateWithFlags(&evGemm, cudaEventDisableTiming);

    cudaEventRecord(evFork, 0);
    cudaStreamWaitEvent(s2, evFork, 0);
    // Chain B (side stream): unscaled GEMM1 -> fp16 messages.
    k_gemm<64, 0><<<dim3(nb_n, 2), 256, 0, s2>>>(x, W1, 128, 128, n);
    cudaEventRecord(evGemm, s2);

    // Chain A (main stream): zero+detect, degree, lookback scan, scatter.
    k_zero_detect<<<nb_n, 256>>>((const int*)ei, n);
    k_deg_count  <<<nb_e, 256>>>(ei, E, n);
    k_scan       <<<nb_scan, 256>>>(n, E);
    k_scatter    <<<nb_e, 256>>>(ei, E, n);

    // Join, fold dinv into layer-1 messages, then the serial tail.
    cudaStreamWaitEvent(0, evGemm, 0);
    k_scale128   <<<nb_sc, 256>>>(n);
    k_agg128     <<<nb_warp, 256>>>(b1, hidden, n);
    k_gemm<40, 1><<<dim3(nb_n, 1), 256>>>(hidden, W2, 40, 40, n);
    k_agg40      <<<nb_warp, 256>>>(b2, logits, n);

    cudaEventDestroy(evFork);
    cudaEventDestroy(evGemm);
    cudaStreamDestroy(s2);
}

// round 7
// speedup vs baseline: 1.0012x; 1.0012x over previous
#include <cuda_runtime.h>
#include <cuda_fp16.h>
#include <stdint.h>

// Fixed problem shape: N=100000 nodes, E=1600000 edges, dims 128 -> 128 -> 40.
#define NMAX 100352
#define EMAX 1600000

// ---------------- device scratch (zero-initialized at load; we re-zero deg/tilestate
// at the END of each call so every graph replay starts clean) ----------------
__device__ int    g_deg[NMAX];                 // must be 0 at call entry
__device__ unsigned int g_tilestate[128];      // must be 0 at call entry
__device__ __align__(16) int g_rowptr[NMAX + 1];
__device__ int    g_cursor[NMAX];
__device__ __align__(16) int g_csrsrc[EMAX];
__device__ float  g_dinv[NMAX];
__device__ __align__(16) __half g_ph[(size_t)NMAX * 128];  // fp16 messages
__device__ float  g_hidden_scratch[(size_t)NMAX * 128];    // fallback hidden storage

// ---------------- packed f32x2 helpers ----------------
__device__ __forceinline__ unsigned long long pack2(float lo, float hi) {
    unsigned long long r;
    asm("mov.b64 %0, {%1, %2};" : "=l"(r) : "f"(lo), "f"(hi));
    return r;
}
__device__ __forceinline__ void unpack2(unsigned long long v, float& lo, float& hi) {
    asm("mov.b64 {%0, %1}, %2;" : "=f"(lo), "=f"(hi) : "l"(v));
}
__device__ __forceinline__ unsigned long long fma2(unsigned long long a,
                                                   unsigned long long b,
                                                   unsigned long long c) {
    unsigned long long d;
    asm("fma.rn.f32x2 %0, %1, %2, %3;" : "=l"(d) : "l"(a), "l"(b), "l"(c));
    return d;
}

// ---------------- inline int64 detection (block-uniform) ----------------
// int64 indices < 2^31 have zero high words -> odd int32 lanes all zero.
__device__ __forceinline__ int detect_idx64(const void* ei) {
    const int* w = (const int*)ei;
    int any = 0;
#pragma unroll
    for (int k = 0; k < 64; ++k) any |= w[2 * k + 1];
    return (any == 0) ? 1 : 0;
}

// ---------------- degree count ----------------
__global__ void k_deg_count(const void* __restrict__ ei, int E, int n) {
    __shared__ int s_idx64;
    if (threadIdx.x == 0) s_idx64 = detect_idx64(ei);
    __syncthreads();
    int e = blockIdx.x * blockDim.x + threadIdx.x;
    if (e < E) {
        int d = s_idx64 ? (int)((const long long*)ei)[(long long)E + e]
                        : ((const int*)ei)[(long long)E + e];
        if ((unsigned)d < (unsigned)n) atomicAdd(&g_deg[d], 1);
    }
}

// ---------------- single-pass decoupled-lookback scan + finish ----------------
__global__ void k_scan(int n, int E) {
    __shared__ int ssum[256];
    __shared__ int s_excl;
    int tid = threadIdx.x;
    int tile = blockIdx.x;
    int base = tile * 1024 + tid * 4;
    int v0 = (base + 0 < n) ? g_deg[base + 0] : 0;
    int v1 = (base + 1 < n) ? g_deg[base + 1] : 0;
    int v2 = (base + 2 < n) ? g_deg[base + 2] : 0;
    int v3 = (base + 3 < n) ? g_deg[base + 3] : 0;
    int p0 = 0, p1 = v0, p2 = v0 + v1, p3 = v0 + v1 + v2;
    int total = p3 + v3;
    ssum[tid] = total;
    __syncthreads();
    for (int off = 1; off < 256; off <<= 1) {
        int v = 0;
        if (tid >= off) v = ssum[tid - off];
        __syncthreads();
        if (tid >= off) ssum[tid] += v;
        __syncthreads();
    }
    int excl_in_tile = ssum[tid] - total;
    int tile_total = ssum[255];

    if (tid == 0) {
        if (tile == 0) {
            __threadfence();
            *(volatile unsigned int*)&g_tilestate[0] = (2u << 30) | (unsigned)tile_total;
            s_excl = 0;
        } else {
            *(volatile unsigned int*)&g_tilestate[tile] = (1u << 30) | (unsigned)tile_total;
            __threadfence();
            int excl = 0;
            int t = tile - 1;
            while (true) {
                unsigned int s = *(volatile unsigned int*)&g_tilestate[t];
                unsigned int f = s >> 30;
                if (f == 0) continue;
                excl += (int)(s & 0x3FFFFFFFu);
                if (f == 2) break;
                --t;
            }
            __threadfence();
            *(volatile unsigned int*)&g_tilestate[tile] = (2u << 30) | (unsigned)(excl + tile_total);
            s_excl = excl;
        }
    }
    __syncthreads();
    int excl = s_excl + excl_in_tile;

#pragma unroll
    for (int q = 0; q < 4; ++q) {
        int i = base + q;
        if (i < n) {
            int pv = excl + ((q == 0) ? p0 : (q == 1) ? p1 : (q == 2) ? p2 : p3);
            g_rowptr[i] = pv;
            g_cursor[i] = pv;
            int dv = (q == 0) ? v0 : (q == 1) ? v1 : (q == 2) ? v2 : v3;
            g_dinv[i] = rsqrtf((float)(dv + 1));
        }
    }
    if (tile == 0 && tid == 0) g_rowptr[n] = E;
}

__global__ void k_scatter(const void* __restrict__ ei, int E, int n) {
    __shared__ int s_idx64;
    if (threadIdx.x == 0) s_idx64 = detect_idx64(ei);
    __syncthreads();
    int e = blockIdx.x * blockDim.x + threadIdx.x;
    if (e < E) {
        int s, d;
        if (s_idx64) {
            s = (int)((const long long*)ei)[e];
            d = (int)((const long long*)ei)[(long long)E + e];
        } else {
            s = ((const int*)ei)[e];
            d = ((const int*)ei)[(long long)E + e];
        }
        if ((unsigned)d < (unsigned)n && (unsigned)s < (unsigned)n) {
            int pos = atomicAdd(&g_cursor[d], 1);
            if (pos < EMAX) g_csrsrc[pos] = s;
        }
    }
}

// ---------------- end-of-call cleanup (runs in the shadow of the agg tail) ----
__global__ void k_cleanup(int n) {
    int i = blockIdx.x * blockDim.x + threadIdx.x;
    if (i < n) g_deg[i] = 0;
    if (i < 128) g_tilestate[i] = 0;
}

// ---------------- GEMM1: g_ph = fp16(X @ W) ; GEMM2 (SCALED): fp16(dinv*(X@W)) ----
template <int FT, int SCALED>
__launch_bounds__(256)
__global__ void k_gemm(const float* __restrict__ X, const float* __restrict__ W,
                       int ldw, int ldp, int n) {
    __shared__ __align__(16) float sW[32 * FT];
    __shared__ __align__(16) float sx[256 * 33];
    const int tid = threadIdx.x;
    const int n0 = blockIdx.x * 256;
    const int f0 = blockIdx.y * FT;
    unsigned long long acc2[FT / 2];
#pragma unroll
    for (int j = 0; j < FT / 2; ++j) acc2[j] = 0ULL;

    for (int kc = 0; kc < 4; ++kc) {
        __syncthreads();
        for (int t = tid; t < 256 * 8; t += 256) {
            int r = t >> 3, c4 = (t & 7) * 4;
            int node = n0 + r;
            float4 xv = make_float4(0.f, 0.f, 0.f, 0.f);
            if (node < n)
                xv = *(const float4*)(X + (size_t)node * 128 + kc * 32 + c4);
            float* d = &sx[r * 33 + c4];
            d[0] = xv.x; d[1] = xv.y; d[2] = xv.z; d[3] = xv.w;
        }
        for (int t = tid; t < 32 * (FT / 4); t += 256) {
            int k = t / (FT / 4), q = t % (FT / 4);
            float4 wv = *(const float4*)(W + (size_t)(kc * 32 + k) * ldw + f0 + q * 4);
            *(float4*)(&sW[k * FT + q * 4]) = wv;
        }
        __syncthreads();
#pragma unroll
        for (int kk = 0; kk < 32; ++kk) {
            float xv = sx[tid * 33 + kk];
            unsigned long long xx = pack2(xv, xv);
            const ulonglong2* wrow = (const ulonglong2*)(&sW[kk * FT]);
#pragma unroll
            for (int j4 = 0; j4 < FT / 4; ++j4) {
                ulonglong2 w = wrow[j4];
                acc2[j4 * 2 + 0] = fma2(xx, w.x, acc2[j4 * 2 + 0]);
                acc2[j4 * 2 + 1] = fma2(xx, w.y, acc2[j4 * 2 + 1]);
            }
        }
    }
    int node = n0 + tid;
    if (node < n) {
        float sc = SCALED ? g_dinv[node] : 1.0f;
        __half2* P = (__half2*)(g_ph + (size_t)node * ldp + f0);
#pragma unroll
        for (int j2 = 0; j2 < FT / 2; ++j2) {
            float2 f;
            unpack2(acc2[j2], f.x, f.y);
            if (SCALED) { f.x *= sc; f.y *= sc; }
            P[j2] = __float22half2_rn(f);
        }
    }
}

// ---------------- aggregation ----------------
__device__ __forceinline__ float4 cvt4(uint2 r) {
    float2 a = __half22float2(*(const __half2*)&r.x);
    float2 b = __half22float2(*(const __half2*)&r.y);
    return make_float4(a.x, a.y, b.x, b.y);
}

// layer 1: unscaled fp16 messages; dinv[src] folded at gather.
__global__ void k_agg128(const float* __restrict__ bias, float* __restrict__ out, int n) {
    int warp = (blockIdx.x * blockDim.x + threadIdx.x) >> 5;
    if (warp >= n) return;
    int lane = threadIdx.x & 31;
    const uint2* p = (const uint2*)g_ph;      // 4 halves per uint2; node stride 32
    float diw = g_dinv[warp];
    float4 self = cvt4(p[(size_t)warp * 32 + lane]);
    float4 acc;
    acc.x = self.x * diw; acc.y = self.y * diw;
    acc.z = self.z * diw; acc.w = self.w * diw;
    int j = g_rowptr[warp];
    int end = g_rowptr[warp + 1];
    for (; j < end && (j & 3); ++j) {
        int s = g_csrsrc[j];
        float d = g_dinv[s];
        float4 v = cvt4(__ldg(&p[(size_t)s * 32 + lane]));
        acc.x = fmaf(v.x, d, acc.x); acc.y = fmaf(v.y, d, acc.y);
        acc.z = fmaf(v.z, d, acc.z); acc.w = fmaf(v.w, d, acc.w);
    }
    for (; j + 4 <= end; j += 4) {
        int4 s4 = __ldg((const int4*)&g_csrsrc[j]);
        float d0 = g_dinv[s4.x], d1 = g_dinv[s4.y], d2 = g_dinv[s4.z], d3 = g_dinv[s4.w];
        float4 v0 = cvt4(__ldg(&p[(size_t)s4.x * 32 + lane]));
        float4 v1 = cvt4(__ldg(&p[(size_t)s4.y * 32 + lane]));
        float4 v2 = cvt4(__ldg(&p[(size_t)s4.z * 32 + lane]));
        float4 v3 = cvt4(__ldg(&p[(size_t)s4.w * 32 + lane]));
        acc.x = fmaf(v0.x, d0, fmaf(v1.x, d1, fmaf(v2.x, d2, fmaf(v3.x, d3, acc.x))));
        acc.y = fmaf(v0.y, d0, fmaf(v1.y, d1, fmaf(v2.y, d2, fmaf(v3.y, d3, acc.y))));
        acc.z = fmaf(v0.z, d0, fmaf(v1.z, d1, fmaf(v2.z, d2, fmaf(v3.z, d3, acc.z))));
        acc.w = fmaf(v0.w, d0, fmaf(v1.w, d1, fmaf(v2.w, d2, fmaf(v3.w, d3, acc.w))));
    }
    for (; j < end; ++j) {
        int s = g_csrsrc[j];
        float d = g_dinv[s];
        float4 v = cvt4(__ldg(&p[(size_t)s * 32 + lane]));
        acc.x = fmaf(v.x, d, acc.x); acc.y = fmaf(v.y, d, acc.y);
        acc.z = fmaf(v.z, d, acc.z); acc.w = fmaf(v.w, d, acc.w);
    }
    float4 bb = ((const float4*)bias)[lane];
    float4 o;
    o.x = fmaxf(fmaf(acc.x, diw, bb.x), 0.f);
    o.y = fmaxf(fmaf(acc.y, diw, bb.y), 0.f);
    o.z = fmaxf(fmaf(acc.z, diw, bb.z), 0.f);
    o.w = fmaxf(fmaf(acc.w, diw, bb.w), 0.f);
    ((float4*)out)[(size_t)warp * 32 + lane] = o;
}

// layer 2: messages pre-scaled by dinv in gemm epilogue.
__global__ void k_agg40(const float* __restrict__ bias, float* __restrict__ out, int n) {
    int warp = (blockIdx.x * blockDim.x + threadIdx.x) >> 5;
    if (warp >= n) return;
    int lane = threadIdx.x & 31;
    bool act = lane < 20;
    const unsigned int* p = (const unsigned int*)g_ph; // 2 halves per uint; node stride 20
    float diw = g_dinv[warp];
    float2 acc = make_float2(0.f, 0.f);
    if (act) {
        float2 self = __half22float2(*(const __half2*)&p[(size_t)warp * 20 + lane]);
        acc = self;
    }
    int j = g_rowptr[warp];
    int end = g_rowptr[warp + 1];
    for (; j < end && (j & 3); ++j) {
        int s = g_csrsrc[j];
        if (act) {
            unsigned int r = __ldg(&p[(size_t)s * 20 + lane]);
            float2 v = __half22float2(*(const __half2*)&r);
            acc.x += v.x; acc.y += v.y;
        }
    }
    for (; j + 4 <= end; j += 4) {
        int4 s4 = __ldg((const int4*)&g_csrsrc[j]);
        if (act) {
            unsigned int r0 = __ldg(&p[(size_t)s4.x * 20 + lane]);
            unsigned int r1 = __ldg(&p[(size_t)s4.y * 20 + lane]);
            unsigned int r2 = __ldg(&p[(size_t)s4.z * 20 + lane]);
            unsigned int r3 = __ldg(&p[(size_t)s4.w * 20 + lane]);
            float2 v0 = __half22float2(*(const __half2*)&r0);
            float2 v1 = __half22float2(*(const __half2*)&r1);
            float2 v2 = __half22float2(*(const __half2*)&r2);
            float2 v3 = __half22float2(*(const __half2*)&r3);
            acc.x += (v0.x + v1.x) + (v2.x + v3.x);
            acc.y += (v0.y + v1.y) + (v2.y + v3.y);
        }
    }
    for (; j < end; ++j) {
        int s = g_csrsrc[j];
        if (act) {
            unsigned int r = __ldg(&p[(size_t)s * 20 + lane]);
            float2 v = __half22float2(*(const __half2*)&r);
            acc.x += v.x; acc.y += v.y;
        }
    }
    if (act) {
        float2 bb = ((const float2*)bias)[lane];
        float2 o;
        o.x = fmaf(acc.x, diw, bb.x);
        o.y = fmaf(acc.y, diw, bb.y);
        ((float2*)out)[(size_t)warp * 20 + lane] = o;
    }
}

// ---------------- launch ----------------
extern "C" void kernel_launch(void* const* d_in, const int* in_sizes, int n_in,
                              void* d_out, int out_size) {
    const float* x  = (const float*)d_in[0];
    const void*  ei = d_in[1];
    const float* W1 = (const float*)d_in[2];
    const float* b1 = (const float*)d_in[3];
    const float* W2 = (const float*)d_in[4];
    const float* b2 = (const float*)d_in[5];

    int n = in_sizes[0] / 128;
    int E = in_sizes[1] / 2;

    float* out    = (float*)d_out;
    float* logits = out;                       // [n, 40]
    float* hidden;
    if ((size_t)out_size >= (size_t)n * (40 + 128)) {
        hidden = out + (size_t)n * 40;         // [n, 128]
    } else {
        cudaGetSymbolAddress((void**)&hidden, g_hidden_scratch);
    }

    int nb_n = (n + 255) / 256;
    int nb_e = (E + 255) / 256;
    int nb_scan = (n + 1023) / 1024;
    int nb_warp = (n + 7) / 8;

    cudaStream_t s2;
    cudaEvent_t evFork, evGemm, evScan, evClean;
    cudaStreamCreateWithFlags(&s2, cudaStreamNonBlocking);
    cudaEventCreateWithFlags(&evFork, cudaEventDisableTiming);
    cudaEventCreateWithFlags(&evGemm, cudaEventDisableTiming);
    cudaEventCreateWithFlags(&evScan, cudaEventDisableTiming);
    cudaEventCreateWithFlags(&evClean, cudaEventDisableTiming);

    // (1) side stream: GEMM1 (fp16 messages, unscaled)
    cudaEventRecord(evFork, 0);
    cudaStreamWaitEvent(s2, evFork, 0);
    k_gemm<64, 0><<<dim3(nb_n, 2), 256, 0, s2>>>(x, W1, 128, 128, n);
    cudaEventRecord(evGemm, s2);

    // (2-4) main stream: CSR chain (g_deg/g_tilestate are zero at entry)
    k_deg_count<<<nb_e, 256>>>(ei, E, n);
    k_scan     <<<nb_scan, 256>>>(n, E);
    cudaEventRecord(evScan, 0);
    k_scatter  <<<nb_e, 256>>>(ei, E, n);

    // (5) side stream: re-zero deg/tilestate for the NEXT call, in the shadow
    cudaStreamWaitEvent(s2, evScan, 0);
    k_cleanup<<<nb_n, 256, 0, s2>>>(n);
    cudaEventRecord(evClean, s2);

    // (6-8) main stream: aggregation tail (6th issued launch -> ncu profiles agg128)
    cudaStreamWaitEvent(0, evGemm, 0);
    k_agg128     <<<nb_warp, 256>>>(b1, hidden, n);
    k_gemm<40, 1><<<dim3(nb_n, 1), 256>>>(hidden, W2, 40, 40, n);
    k_agg40      <<<nb_warp, 256>>>(b2, logits, n);

    // rejoin side stream before capture ends
    cudaStreamWaitEvent(0, evClean, 0);

    cudaEventDestroy(evFork);
    cudaEventDestroy(evGemm);
    cudaEventDestroy(evScan);
    cudaEventDestroy(evClean);
    cudaStreamDestroy(s2);
}

// round 8
// speedup vs baseline: 1.3901x; 1.3885x over previous
#include <cuda_runtime.h>
#include <cuda_fp16.h>
#include <stdint.h>

// Fixed problem shape: N=100000 nodes, E=1600000 edges, dims 128 -> 128 -> 40.
#define NMAX 100352
#define EMAX 1600000

// ---------------- device scratch (zero-initialized at load; scan/scatter
// re-zero g_deg/g_tilestate themselves so every replay starts clean) --------
__device__ int    g_deg[NMAX];                 // 0 at call entry (self-cleaned)
__device__ unsigned int g_tilestate[128];      // 0 at call entry (self-cleaned)
__device__ __align__(16) int g_rowptr[NMAX + 1];
__device__ int    g_cursor[NMAX];
__device__ __align__(16) int g_csrsrc[EMAX];
__device__ float  g_dinv[NMAX];
__device__ __align__(16) __half g_ph[(size_t)NMAX * 128];  // fp16 messages
__device__ float  g_hidden_scratch[(size_t)NMAX * 128];    // fallback hidden storage

// ---------------- packed f32x2 helpers (SIMT gemm40) ----------------
__device__ __forceinline__ unsigned long long pack2(float lo, float hi) {
    unsigned long long r;
    asm("mov.b64 %0, {%1, %2};" : "=l"(r) : "f"(lo), "f"(hi));
    return r;
}
__device__ __forceinline__ void unpack2(unsigned long long v, float& lo, float& hi) {
    asm("mov.b64 {%0, %1}, %2;" : "=f"(lo), "=f"(hi) : "l"(v));
}
__device__ __forceinline__ unsigned long long fma2(unsigned long long a,
                                                   unsigned long long b,
                                                   unsigned long long c) {
    unsigned long long d;
    asm("fma.rn.f32x2 %0, %1, %2, %3;" : "=l"(d) : "l"(a), "l"(b), "l"(c));
    return d;
}

// ---------------- inline int64 detection (block-uniform) ----------------
__device__ __forceinline__ int detect_idx64(const void* ei) {
    const int* w = (const int*)ei;
    int any = 0;
#pragma unroll
    for (int k = 0; k < 64; ++k) any |= w[2 * k + 1];
    return (any == 0) ? 1 : 0;
}

// ---------------- degree count ----------------
__global__ void k_deg_count(const void* __restrict__ ei, int E, int n) {
    __shared__ int s_idx64;
    if (threadIdx.x == 0) s_idx64 = detect_idx64(ei);
    __syncthreads();
    int e = blockIdx.x * blockDim.x + threadIdx.x;
    if (e < E) {
        int d = s_idx64 ? (int)((const long long*)ei)[(long long)E + e]
                        : ((const int*)ei)[(long long)E + e];
        if ((unsigned)d < (unsigned)n) atomicAdd(&g_deg[d], 1);
    }
}

// ---------------- single-pass decoupled-lookback scan + finish + self-clean ----
__global__ void k_scan(int n, int E) {
    __shared__ int ssum[256];
    __shared__ int s_excl;
    int tid = threadIdx.x;
    int tile = blockIdx.x;
    int base = tile * 1024 + tid * 4;
    int v0 = (base + 0 < n) ? g_deg[base + 0] : 0;
    int v1 = (base + 1 < n) ? g_deg[base + 1] : 0;
    int v2 = (base + 2 < n) ? g_deg[base + 2] : 0;
    int v3 = (base + 3 < n) ? g_deg[base + 3] : 0;
    int p0 = 0, p1 = v0, p2 = v0 + v1, p3 = v0 + v1 + v2;
    int total = p3 + v3;
    ssum[tid] = total;
    __syncthreads();
    for (int off = 1; off < 256; off <<= 1) {
        int v = 0;
        if (tid >= off) v = ssum[tid - off];
        __syncthreads();
        if (tid >= off) ssum[tid] += v;
        __syncthreads();
    }
    int excl_in_tile = ssum[tid] - total;
    int tile_total = ssum[255];

    if (tid == 0) {
        if (tile == 0) {
            __threadfence();
            *(volatile unsigned int*)&g_tilestate[0] = (2u << 30) | (unsigned)tile_total;
            s_excl = 0;
        } else {
            *(volatile unsigned int*)&g_tilestate[tile] = (1u << 30) | (unsigned)tile_total;
            __threadfence();
            int excl = 0;
            int t = tile - 1;
            while (true) {
                unsigned int s = *(volatile unsigned int*)&g_tilestate[t];
                unsigned int f = s >> 30;
                if (f == 0) continue;
                excl += (int)(s & 0x3FFFFFFFu);
                if (f == 2) break;
                --t;
            }
            __threadfence();
            *(volatile unsigned int*)&g_tilestate[tile] = (2u << 30) | (unsigned)(excl + tile_total);
            s_excl = excl;
        }
    }
    __syncthreads();
    int excl = s_excl + excl_in_tile;

#pragma unroll
    for (int q = 0; q < 4; ++q) {
        int i = base + q;
        if (i < n) {
            int pv = excl + ((q == 0) ? p0 : (q == 1) ? p1 : (q == 2) ? p2 : p3);
            g_rowptr[i] = pv;
            g_cursor[i] = pv;
            int dv = (q == 0) ? v0 : (q == 1) ? v1 : (q == 2) ? v2 : v3;
            g_dinv[i] = rsqrtf((float)(dv + 1));
            g_deg[i] = 0;                      // self-clean for next call
        }
    }
    if (tile == 0 && tid == 0) g_rowptr[n] = E;
}

__global__ void k_scatter(const void* __restrict__ ei, int E, int n) {
    __shared__ int s_idx64;
    if (threadIdx.x == 0) s_idx64 = detect_idx64(ei);
    __syncthreads();
    // self-clean tilestate for next call (scan is fully done by stream order)
    if (blockIdx.x == 0 && threadIdx.x < 128) g_tilestate[threadIdx.x] = 0;
    int e = blockIdx.x * blockDim.x + threadIdx.x;
    if (e < E) {
        int s, d;
        if (s_idx64) {
            s = (int)((const long long*)ei)[e];
            d = (int)((const long long*)ei)[(long long)E + e];
        } else {
            s = ((const int*)ei)[e];
            d = ((const int*)ei)[(long long)E + e];
        }
        if ((unsigned)d < (unsigned)n && (unsigned)s < (unsigned)n) {
            int pos = atomicAdd(&g_cursor[d], 1);
            if (pos < EMAX) g_csrsrc[pos] = s;
        }
    }
}

// ---------------- TF32 tensor-core GEMM (layer 1): g_ph = fp16(X @ W1) ----
// Block: 256 threads = 8 warps (2 M x 4 N). Block tile 128 nodes x 128 out.
// Warp tile 64x32 = 4 m-tiles x 4 n-tiles of m16n8k8. K chunked by 32.
__device__ __forceinline__ unsigned int f2tf32(float f) {
    unsigned int u;
    asm("cvt.rna.tf32.f32 %0, %1;" : "=r"(u) : "f"(f));
    return u;
}

#define XS_STRIDE 36
#define WS_STRIDE 132

__launch_bounds__(256)
__global__ void k_gemm_tc(const float* __restrict__ X, const float* __restrict__ W, int n) {
    __shared__ unsigned int Xs[128 * XS_STRIDE];   // [row][k] tf32, 18KB
    __shared__ unsigned int Ws[32 * WS_STRIDE];    // [k][col] tf32, 16.9KB
    const int tid = threadIdx.x;
    const int warp = tid >> 5;
    const int lane = tid & 31;
    const int wm = warp >> 2;          // 0..1
    const int wn = warp & 3;           // 0..3
    const int grp = lane >> 2;         // 0..7
    const int qid = lane & 3;          // 0..3
    const int n0 = blockIdx.x * 128;

    float acc[4][4][4];
#pragma unroll
    for (int mt = 0; mt < 4; ++mt)
#pragma unroll
        for (int nt = 0; nt < 4; ++nt)
#pragma unroll
            for (int r = 0; r < 4; ++r) acc[mt][nt][r] = 0.f;

    for (int kc = 0; kc < 4; ++kc) {
        __syncthreads();
        // fill Xs: 128 rows x 32 k (coalesced)
#pragma unroll
        for (int i = 0; i < 16; ++i) {
            int idx = tid + i * 256;
            int row = idx >> 5, col = idx & 31;
            int node = n0 + row;
            float v = (node < n) ? X[(size_t)node * 128 + kc * 32 + col] : 0.f;
            Xs[row * XS_STRIDE + col] = f2tf32(v);
        }
        // fill Ws: 32 k x 128 cols (coalesced)
#pragma unroll
        for (int i = 0; i < 16; ++i) {
            int idx = tid + i * 256;
            int k = idx >> 7, col = idx & 127;
            Ws[k * WS_STRIDE + col] = f2tf32(W[(size_t)(kc * 32 + k) * 128 + col]);
        }
        __syncthreads();
#pragma unroll
        for (int kk = 0; kk < 4; ++kk) {
            const int k8 = kk * 8;
            unsigned int af[4][4];
#pragma unroll
            for (int mt = 0; mt < 4; ++mt) {
                int rbase = wm * 64 + mt * 16;
                af[mt][0] = Xs[(rbase + grp) * XS_STRIDE + k8 + qid];
                af[mt][1] = Xs[(rbase + grp + 8) * XS_STRIDE + k8 + qid];
                af[mt][2] = Xs[(rbase + grp) * XS_STRIDE + k8 + qid + 4];
                af[mt][3] = Xs[(rbase + grp + 8) * XS_STRIDE + k8 + qid + 4];
            }
            unsigned int bf[4][2];
#pragma unroll
            for (int nt = 0; nt < 4; ++nt) {
                int cbase = wn * 32 + nt * 8;
                bf[nt][0] = Ws[(k8 + qid) * WS_STRIDE + cbase + grp];
                bf[nt][1] = Ws[(k8 + qid + 4) * WS_STRIDE + cbase + grp];
            }
#pragma unroll
            for (int mt = 0; mt < 4; ++mt)
#pragma unroll
                for (int nt = 0; nt < 4; ++nt) {
                    asm volatile(
                        "mma.sync.aligned.m16n8k8.row.col.f32.tf32.tf32.f32 "
                        "{%0,%1,%2,%3}, {%4,%5,%6,%7}, {%8,%9}, {%0,%1,%2,%3};"
                        : "+f"(acc[mt][nt][0]), "+f"(acc[mt][nt][1]),
                          "+f"(acc[mt][nt][2]), "+f"(acc[mt][nt][3])
                        : "r"(af[mt][0]), "r"(af[mt][1]), "r"(af[mt][2]), "r"(af[mt][3]),
                          "r"(bf[nt][0]), "r"(bf[nt][1]));
                }
        }
    }
    // epilogue: fp16 store. D tile layout: c0,c1 -> row grp, cols 2q,2q+1; c2,c3 -> row grp+8.
#pragma unroll
    for (int mt = 0; mt < 4; ++mt) {
        int r0 = n0 + wm * 64 + mt * 16 + grp;
        int r1 = r0 + 8;
#pragma unroll
        for (int nt = 0; nt < 4; ++nt) {
            int col = wn * 32 + nt * 8 + 2 * qid;
            if (r0 < n) {
                __half2 h = __float22half2_rn(make_float2(acc[mt][nt][0], acc[mt][nt][1]));
                *(__half2*)(g_ph + (size_t)r0 * 128 + col) = h;
            }
            if (r1 < n) {
                __half2 h = __float22half2_rn(make_float2(acc[mt][nt][2], acc[mt][nt][3]));
                *(__half2*)(g_ph + (size_t)r1 * 128 + col) = h;
            }
        }
    }
}

// ---------------- SIMT GEMM (layer 2, scaled): g_ph = fp16(dinv*(X@W2)) ----
template <int FT>
__launch_bounds__(256)
__global__ void k_gemm(const float* __restrict__ X, const float* __restrict__ W,
                       int ldw, int ldp, int n) {
    __shared__ __align__(16) float sW[32 * FT];
    __shared__ __align__(16) float sx[256 * 33];
    const int tid = threadIdx.x;
    const int n0 = blockIdx.x * 256;
    unsigned long long acc2[FT / 2];
#pragma unroll
    for (int j = 0; j < FT / 2; ++j) acc2[j] = 0ULL;

    for (int kc = 0; kc < 4; ++kc) {
        __syncthreads();
        for (int t = tid; t < 256 * 8; t += 256) {
            int r = t >> 3, c4 = (t & 7) * 4;
            int node = n0 + r;
            float4 xv = make_float4(0.f, 0.f, 0.f, 0.f);
            if (node < n)
                xv = *(const float4*)(X + (size_t)node * 128 + kc * 32 + c4);
            float* d = &sx[r * 33 + c4];
            d[0] = xv.x; d[1] = xv.y; d[2] = xv.z; d[3] = xv.w;
        }
        for (int t = tid; t < 32 * (FT / 4); t += 256) {
            int k = t / (FT / 4), q = t % (FT / 4);
            float4 wv = *(const float4*)(W + (size_t)(kc * 32 + k) * ldw + q * 4);
            *(float4*)(&sW[k * FT + q * 4]) = wv;
        }
        __syncthreads();
#pragma unroll
        for (int kk = 0; kk < 32; ++kk) {
            float xv = sx[tid * 33 + kk];
            unsigned long long xx = pack2(xv, xv);
            const ulonglong2* wrow = (const ulonglong2*)(&sW[kk * FT]);
#pragma unroll
            for (int j4 = 0; j4 < FT / 4; ++j4) {
                ulonglong2 w = wrow[j4];
                acc2[j4 * 2 + 0] = fma2(xx, w.x, acc2[j4 * 2 + 0]);
                acc2[j4 * 2 + 1] = fma2(xx, w.y, acc2[j4 * 2 + 1]);
            }
        }
    }
    int node = n0 + tid;
    if (node < n) {
        float sc = g_dinv[node];
        __half2* P = (__half2*)(g_ph + (size_t)node * ldp);
#pragma unroll
        for (int j2 = 0; j2 < FT / 2; ++j2) {
            float2 f;
            unpack2(acc2[j2], f.x, f.y);
            f.x *= sc; f.y *= sc;
            P[j2] = __float22half2_rn(f);
        }
    }
}

// ---------------- aggregation ----------------
__device__ __forceinline__ float4 cvt4(uint2 r) {
    float2 a = __half22float2(*(const __half2*)&r.x);
    float2 b = __half22float2(*(const __half2*)&r.y);
    return make_float4(a.x, a.y, b.x, b.y);
}

// layer 1: unscaled fp16 messages; dinv[src] folded at gather.
__global__ void k_agg128(const float* __restrict__ bias, float* __restrict__ out, int n) {
    int warp = (blockIdx.x * blockDim.x + threadIdx.x) >> 5;
    if (warp >= n) return;
    int lane = threadIdx.x & 31;
    const uint2* p = (const uint2*)g_ph;
    float diw = g_dinv[warp];
    float4 self = cvt4(p[(size_t)warp * 32 + lane]);
    float4 acc;
    acc.x = self.x * diw; acc.y = self.y * diw;
    acc.z = self.z * diw; acc.w = self.w * diw;
    int j = g_rowptr[warp];
    int end = g_rowptr[warp + 1];
    for (; j < end && (j & 3); ++j) {
        int s = g_csrsrc[j];
        float d = g_dinv[s];
        float4 v = cvt4(__ldg(&p[(size_t)s * 32 + lane]));
        acc.x = fmaf(v.x, d, acc.x); acc.y = fmaf(v.y, d, acc.y);
        acc.z = fmaf(v.z, d, acc.z); acc.w = fmaf(v.w, d, acc.w);
    }
    for (; j + 4 <= end; j += 4) {
        int4 s4 = __ldg((const int4*)&g_csrsrc[j]);
        float d0 = g_dinv[s4.x], d1 = g_dinv[s4.y], d2 = g_dinv[s4.z], d3 = g_dinv[s4.w];
        float4 v0 = cvt4(__ldg(&p[(size_t)s4.x * 32 + lane]));
        float4 v1 = cvt4(__ldg(&p[(size_t)s4.y * 32 + lane]));
        float4 v2 = cvt4(__ldg(&p[(size_t)s4.z * 32 + lane]));
        float4 v3 = cvt4(__ldg(&p[(size_t)s4.w * 32 + lane]));
        acc.x = fmaf(v0.x, d0, fmaf(v1.x, d1, fmaf(v2.x, d2, fmaf(v3.x, d3, acc.x))));
        acc.y = fmaf(v0.y, d0, fmaf(v1.y, d1, fmaf(v2.y, d2, fmaf(v3.y, d3, acc.y))));
        acc.z = fmaf(v0.z, d0, fmaf(v1.z, d1, fmaf(v2.z, d2, fmaf(v3.z, d3, acc.z))));
        acc.w = fmaf(v0.w, d0, fmaf(v1.w, d1, fmaf(v2.w, d2, fmaf(v3.w, d3, acc.w))));
    }
    for (; j < end; ++j) {
        int s = g_csrsrc[j];
        float d = g_dinv[s];
        float4 v = cvt4(__ldg(&p[(size_t)s * 32 + lane]));
        acc.x = fmaf(v.x, d, acc.x); acc.y = fmaf(v.y, d, acc.y);
        acc.z = fmaf(v.z, d, acc.z); acc.w = fmaf(v.w, d, acc.w);
    }
    float4 bb = ((const float4*)bias)[lane];
    float4 o;
    o.x = fmaxf(fmaf(acc.x, diw, bb.x), 0.f);
    o.y = fmaxf(fmaf(acc.y, diw, bb.y), 0.f);
    o.z = fmaxf(fmaf(acc.z, diw, bb.z), 0.f);
    o.w = fmaxf(fmaf(acc.w, diw, bb.w), 0.f);
    ((float4*)out)[(size_t)warp * 32 + lane] = o;
}

// layer 2: messages pre-scaled by dinv in gemm epilogue.
__global__ void k_agg40(const float* __restrict__ bias, float* __restrict__ out, int n) {
    int warp = (blockIdx.x * blockDim.x + threadIdx.x) >> 5;
    if (warp >= n) return;
    int lane = threadIdx.x & 31;
    bool act = lane < 20;
    const unsigned int* p = (const unsigned int*)g_ph;
    float diw = g_dinv[warp];
    float2 acc = make_float2(0.f, 0.f);
    if (act) acc = __half22float2(*(const __half2*)&p[(size_t)warp * 20 + lane]);
    int j = g_rowptr[warp];
    int end = g_rowptr[warp + 1];
    for (; j < end && (j & 3); ++j) {
        int s = g_csrsrc[j];
        if (act) {
            unsigned int r = __ldg(&p[(size_t)s * 20 + lane]);
            float2 v = __half22float2(*(const __half2*)&r);
            acc.x += v.x; acc.y += v.y;
        }
    }
    for (; j + 4 <= end; j += 4) {
        int4 s4 = __ldg((const int4*)&g_csrsrc[j]);
        if (act) {
            unsigned int r0 = __ldg(&p[(size_t)s4.x * 20 + lane]);
            unsigned int r1 = __ldg(&p[(size_t)s4.y * 20 + lane]);
            unsigned int r2 = __ldg(&p[(size_t)s4.z * 20 + lane]);
            unsigned int r3 = __ldg(&p[(size_t)s4.w * 20 + lane]);
            float2 v0 = __half22float2(*(const __half2*)&r0);
            float2 v1 = __half22float2(*(const __half2*)&r1);
            float2 v2 = __half22float2(*(const __half2*)&r2);
            float2 v3 = __half22float2(*(const __half2*)&r3);
            acc.x += (v0.x + v1.x) + (v2.x + v3.x);
            acc.y += (v0.y + v1.y) + (v2.y + v3.y);
        }
    }
    for (; j < end; ++j) {
        int s = g_csrsrc[j];
        if (act) {
            unsigned int r = __ldg(&p[(size_t)s * 20 + lane]);
            float2 v = __half22float2(*(const __half2*)&r);
            acc.x += v.x; acc.y += v.y;
        }
    }
    if (act) {
        float2 bb = ((const float2*)bias)[lane];
        float2 o;
        o.x = fmaf(acc.x, diw, bb.x);
        o.y = fmaf(acc.y, diw, bb.y);
        ((float2*)out)[(size_t)warp * 20 + lane] = o;
    }
}

// ---------------- launch ----------------
extern "C" void kernel_launch(void* const* d_in, const int* in_sizes, int n_in,
                              void* d_out, int out_size) {
    const float* x  = (const float*)d_in[0];
    const void*  ei = d_in[1];
    const float* W1 = (const float*)d_in[2];
    const float* b1 = (const float*)d_in[3];
    const float* W2 = (const float*)d_in[4];
    const float* b2 = (const float*)d_in[5];

    int n = in_sizes[0] / 128;
    int E = in_sizes[1] / 2;

    float* out    = (float*)d_out;
    float* logits = out;                       // [n, 40]
    float* hidden;
    if ((size_t)out_size >= (size_t)n * (40 + 128)) {
        hidden = out + (size_t)n * 40;         // [n, 128]
    } else {
        cudaGetSymbolAddress((void**)&hidden, g_hidden_scratch);
    }

    int nb_n  = (n + 255) / 256;
    int nb_tc = (n + 127) / 128;
    int nb_e  = (E + 255) / 256;
    int nb_scan = (n + 1023) / 1024;
    int nb_warp = (n + 7) / 8;

    cudaStream_t s2;
    cudaEvent_t evFork, evGemm;
    cudaStreamCreateWithFlags(&s2, cudaStreamNonBlocking);
    cudaEventCreateWithFlags(&evFork, cudaEventDisableTiming);
    cudaEventCreateWithFlags(&evGemm, cudaEventDisableTiming);

    // side stream: tensor-core GEMM1 (fp16 messages, unscaled)
    cudaEventRecord(evFork, 0);
    cudaStreamWaitEvent(s2, evFork, 0);
    k_gemm_tc<<<nb_tc, 256, 0, s2>>>(x, W1, n);
    cudaEventRecord(evGemm, s2);

    // main stream: CSR chain (self-cleaning)
    k_deg_count<<<nb_e, 256>>>(ei, E, n);
    k_scan     <<<nb_scan, 256>>>(n, E);
    k_scatter  <<<nb_e, 256>>>(ei, E, n);

    // join, then serial tail
    cudaStreamWaitEvent(0, evGemm, 0);
    k_agg128  <<<nb_warp, 256>>>(b1, hidden, n);
    k_gemm<40><<<nb_n, 256>>>(hidden, W2, 40, 40, n);
    k_agg40   <<<nb_warp, 256>>>(b2, logits, n);

    cudaEventDestroy(evFork);
    cudaEventDestroy(evGemm);
    cudaStreamDestroy(s2);
}

// round 9
// speedup vs baseline: 1.4443x; 1.0390x over previous
#include <cuda_runtime.h>
#include <cuda_fp16.h>
#include <stdint.h>

// Fixed problem shape: N=100000 nodes, E=1600000 edges, dims 128 -> 128 -> 40.
#define NMAX 100352
#define EMAX 1600000

// ---------------- device scratch (zero-initialized at load; scan/scatter
// re-zero g_deg/g_tilestate themselves so every replay starts clean) --------
__device__ int    g_deg[NMAX];                 // 0 at call entry (self-cleaned)
__device__ unsigned int g_tilestate[128];      // 0 at call entry (self-cleaned)
__device__ __align__(16) int g_rowptr[NMAX + 1];
__device__ int    g_cursor[NMAX];
__device__ __align__(16) int g_csrsrc[EMAX];
__device__ float  g_dinv[NMAX];
__device__ __align__(16) __half g_ph[(size_t)NMAX * 128];  // fp16 messages
__device__ float  g_hidden_scratch[(size_t)NMAX * 128];    // fallback hidden storage

// ---------------- inline int64 detection (block-uniform) ----------------
__device__ __forceinline__ int detect_idx64(const void* ei) {
    const int* w = (const int*)ei;
    int any = 0;
#pragma unroll
    for (int k = 0; k < 64; ++k) any |= w[2 * k + 1];
    return (any == 0) ? 1 : 0;
}

// ---------------- degree count (2 edges per thread) ----------------
__global__ void k_deg_count(const void* __restrict__ ei, int E, int n) {
    __shared__ int s_idx64;
    if (threadIdx.x == 0) s_idx64 = detect_idx64(ei);
    __syncthreads();
    int t = blockIdx.x * blockDim.x + threadIdx.x;
    int e0 = t * 2;
    if (e0 + 1 < E) {
        int d0, d1;
        if (s_idx64) {
            const long long* dst = (const long long*)ei + E;
            longlong2 v = ((const longlong2*)dst)[t];
            d0 = (int)v.x; d1 = (int)v.y;
        } else {
            const int* dst = (const int*)ei + E;
            int2 v = ((const int2*)dst)[t];
            d0 = v.x; d1 = v.y;
        }
        if ((unsigned)d0 < (unsigned)n) atomicAdd(&g_deg[d0], 1);
        if ((unsigned)d1 < (unsigned)n) atomicAdd(&g_deg[d1], 1);
    } else if (e0 < E) {
        int d = s_idx64 ? (int)((const long long*)ei)[(long long)E + e0]
                        : ((const int*)ei)[(long long)E + e0];
        if ((unsigned)d < (unsigned)n) atomicAdd(&g_deg[d], 1);
    }
}

// ---------------- single-pass decoupled-lookback scan + finish + self-clean ----
__global__ void k_scan(int n, int E) {
    __shared__ int ssum[256];
    __shared__ int s_excl;
    int tid = threadIdx.x;
    int tile = blockIdx.x;
    int base = tile * 1024 + tid * 4;
    int v0 = (base + 0 < n) ? g_deg[base + 0] : 0;
    int v1 = (base + 1 < n) ? g_deg[base + 1] : 0;
    int v2 = (base + 2 < n) ? g_deg[base + 2] : 0;
    int v3 = (base + 3 < n) ? g_deg[base + 3] : 0;
    int p0 = 0, p1 = v0, p2 = v0 + v1, p3 = v0 + v1 + v2;
    int total = p3 + v3;
    ssum[tid] = total;
    __syncthreads();
    for (int off = 1; off < 256; off <<= 1) {
        int v = 0;
        if (tid >= off) v = ssum[tid - off];
        __syncthreads();
        if (tid >= off) ssum[tid] += v;
        __syncthreads();
    }
    int excl_in_tile = ssum[tid] - total;
    int tile_total = ssum[255];

    if (tid == 0) {
        if (tile == 0) {
            __threadfence();
            *(volatile unsigned int*)&g_tilestate[0] = (2u << 30) | (unsigned)tile_total;
            s_excl = 0;
        } else {
            *(volatile unsigned int*)&g_tilestate[tile] = (1u << 30) | (unsigned)tile_total;
            __threadfence();
            int excl = 0;
            int t = tile - 1;
            while (true) {
                unsigned int s = *(volatile unsigned int*)&g_tilestate[t];
                unsigned int f = s >> 30;
                if (f == 0) continue;
                excl += (int)(s & 0x3FFFFFFFu);
                if (f == 2) break;
                --t;
            }
            __threadfence();
            *(volatile unsigned int*)&g_tilestate[tile] = (2u << 30) | (unsigned)(excl + tile_total);
            s_excl = excl;
        }
    }
    __syncthreads();
    int excl = s_excl + excl_in_tile;

#pragma unroll
    for (int q = 0; q < 4; ++q) {
        int i = base + q;
        if (i < n) {
            int pv = excl + ((q == 0) ? p0 : (q == 1) ? p1 : (q == 2) ? p2 : p3);
            g_rowptr[i] = pv;
            g_cursor[i] = pv;
            int dv = (q == 0) ? v0 : (q == 1) ? v1 : (q == 2) ? v2 : v3;
            g_dinv[i] = rsqrtf((float)(dv + 1));
            g_deg[i] = 0;                      // self-clean for next call
        }
    }
    if (tile == 0 && tid == 0) g_rowptr[n] = E;
}

// ---------------- scatter (2 edges per thread) ----------------
__global__ void k_scatter(const void* __restrict__ ei, int E, int n) {
    __shared__ int s_idx64;
    if (threadIdx.x == 0) s_idx64 = detect_idx64(ei);
    __syncthreads();
    if (blockIdx.x == 0 && threadIdx.x < 128) g_tilestate[threadIdx.x] = 0;
    int t = blockIdx.x * blockDim.x + threadIdx.x;
    int e0 = t * 2;
    if (e0 + 1 < E) {
        int s0, s1, d0, d1;
        if (s_idx64) {
            const long long* src = (const long long*)ei;
            const long long* dst = src + E;
            longlong2 sv = ((const longlong2*)src)[t];
            longlong2 dv = ((const longlong2*)dst)[t];
            s0 = (int)sv.x; s1 = (int)sv.y; d0 = (int)dv.x; d1 = (int)dv.y;
        } else {
            const int* src = (const int*)ei;
            const int* dst = src + E;
            int2 sv = ((const int2*)src)[t];
            int2 dv = ((const int2*)dst)[t];
            s0 = sv.x; s1 = sv.y; d0 = dv.x; d1 = dv.y;
        }
        if ((unsigned)d0 < (unsigned)n && (unsigned)s0 < (unsigned)n) {
            int pos = atomicAdd(&g_cursor[d0], 1);
            if (pos < EMAX) g_csrsrc[pos] = s0;
        }
        if ((unsigned)d1 < (unsigned)n && (unsigned)s1 < (unsigned)n) {
            int pos = atomicAdd(&g_cursor[d1], 1);
            if (pos < EMAX) g_csrsrc[pos] = s1;
        }
    } else if (e0 < E) {
        int s, d;
        if (s_idx64) {
            s = (int)((const long long*)ei)[e0];
            d = (int)((const long long*)ei)[(long long)E + e0];
        } else {
            s = ((const int*)ei)[e0];
            d = ((const int*)ei)[(long long)E + e0];
        }
        if ((unsigned)d < (unsigned)n && (unsigned)s < (unsigned)n) {
            int pos = atomicAdd(&g_cursor[d], 1);
            if (pos < EMAX) g_csrsrc[pos] = s;
        }
    }
}

// ---------------- TF32 helpers ----------------
__device__ __forceinline__ unsigned int f2tf32(float f) {
    unsigned int u;
    asm("cvt.rna.tf32.f32 %0, %1;" : "=r"(u) : "f"(f));
    return u;
}
#define XS_STRIDE 36
#define WS_STRIDE 132

// ---------------- TF32 GEMM layer 1: g_ph = fp16(X @ W1), 128x128 block tile ----
__launch_bounds__(256)
__global__ void k_gemm_tc(const float* __restrict__ X, const float* __restrict__ W, int n) {
    __shared__ unsigned int Xs[128 * XS_STRIDE];
    __shared__ unsigned int Ws[32 * WS_STRIDE];
    const int tid = threadIdx.x;
    const int warp = tid >> 5;
    const int lane = tid & 31;
    const int wm = warp >> 2;
    const int wn = warp & 3;
    const int grp = lane >> 2;
    const int qid = lane & 3;
    const int n0 = blockIdx.x * 128;

    float acc[4][4][4];
#pragma unroll
    for (int mt = 0; mt < 4; ++mt)
#pragma unroll
        for (int nt = 0; nt < 4; ++nt)
#pragma unroll
            for (int r = 0; r < 4; ++r) acc[mt][nt][r] = 0.f;

    for (int kc = 0; kc < 4; ++kc) {
        __syncthreads();
#pragma unroll
        for (int i = 0; i < 16; ++i) {
            int idx = tid + i * 256;
            int row = idx >> 5, col = idx & 31;
            int node = n0 + row;
            float v = (node < n) ? X[(size_t)node * 128 + kc * 32 + col] : 0.f;
            Xs[row * XS_STRIDE + col] = f2tf32(v);
        }
#pragma unroll
        for (int i = 0; i < 16; ++i) {
            int idx = tid + i * 256;
            int k = idx >> 7, col = idx & 127;
            Ws[k * WS_STRIDE + col] = f2tf32(W[(size_t)(kc * 32 + k) * 128 + col]);
        }
        __syncthreads();
#pragma unroll
        for (int kk = 0; kk < 4; ++kk) {
            const int k8 = kk * 8;
            unsigned int af[4][4];
#pragma unroll
            for (int mt = 0; mt < 4; ++mt) {
                int rbase = wm * 64 + mt * 16;
                af[mt][0] = Xs[(rbase + grp) * XS_STRIDE + k8 + qid];
                af[mt][1] = Xs[(rbase + grp + 8) * XS_STRIDE + k8 + qid];
                af[mt][2] = Xs[(rbase + grp) * XS_STRIDE + k8 + qid + 4];
                af[mt][3] = Xs[(rbase + grp + 8) * XS_STRIDE + k8 + qid + 4];
            }
            unsigned int bf[4][2];
#pragma unroll
            for (int nt = 0; nt < 4; ++nt) {
                int cbase = wn * 32 + nt * 8;
                bf[nt][0] = Ws[(k8 + qid) * WS_STRIDE + cbase + grp];
                bf[nt][1] = Ws[(k8 + qid + 4) * WS_STRIDE + cbase + grp];
            }
#pragma unroll
            for (int mt = 0; mt < 4; ++mt)
#pragma unroll
                for (int nt = 0; nt < 4; ++nt) {
                    asm volatile(
                        "mma.sync.aligned.m16n8k8.row.col.f32.tf32.tf32.f32 "
                        "{%0,%1,%2,%3}, {%4,%5,%6,%7}, {%8,%9}, {%0,%1,%2,%3};"
                        : "+f"(acc[mt][nt][0]), "+f"(acc[mt][nt][1]),
                          "+f"(acc[mt][nt][2]), "+f"(acc[mt][nt][3])
                        : "r"(af[mt][0]), "r"(af[mt][1]), "r"(af[mt][2]), "r"(af[mt][3]),
                          "r"(bf[nt][0]), "r"(bf[nt][1]));
                }
        }
    }
#pragma unroll
    for (int mt = 0; mt < 4; ++mt) {
        int r0 = n0 + wm * 64 + mt * 16 + grp;
        int r1 = r0 + 8;
#pragma unroll
        for (int nt = 0; nt < 4; ++nt) {
            int col = wn * 32 + nt * 8 + 2 * qid;
            if (r0 < n) {
                __half2 h = __float22half2_rn(make_float2(acc[mt][nt][0], acc[mt][nt][1]));
                *(__half2*)(g_ph + (size_t)r0 * 128 + col) = h;
            }
            if (r1 < n) {
                __half2 h = __float22half2_rn(make_float2(acc[mt][nt][2], acc[mt][nt][3]));
                *(__half2*)(g_ph + (size_t)r1 * 128 + col) = h;
            }
        }
    }
}

// ---------------- TF32 GEMM layer 2: g_ph = fp16(dinv * (hidden @ W2)) ----
// Block 256 threads = 8 warps; block tile 128 nodes x 40 cols.
// Warp w: rows w*16..w*16+15 (one m16 tile), 5 n-tiles of 8 cols.
#define W2S_STRIDE 44
__launch_bounds__(256)
__global__ void k_gemm40_tc(const float* __restrict__ X, const float* __restrict__ W, int n) {
    __shared__ unsigned int Xs[128 * XS_STRIDE];
    __shared__ unsigned int Ws[32 * W2S_STRIDE];
    const int tid = threadIdx.x;
    const int warp = tid >> 5;
    const int lane = tid & 31;
    const int grp = lane >> 2;
    const int qid = lane & 3;
    const int n0 = blockIdx.x * 128;

    float acc[5][4];
#pragma unroll
    for (int nt = 0; nt < 5; ++nt)
#pragma unroll
        for (int r = 0; r < 4; ++r) acc[nt][r] = 0.f;

    for (int kc = 0; kc < 4; ++kc) {
        __syncthreads();
#pragma unroll
        for (int i = 0; i < 16; ++i) {
            int idx = tid + i * 256;
            int row = idx >> 5, col = idx & 31;
            int node = n0 + row;
            float v = (node < n) ? X[(size_t)node * 128 + kc * 32 + col] : 0.f;
            Xs[row * XS_STRIDE + col] = f2tf32(v);
        }
        // Ws: 32 k x 40 cols = 1280 elems
        for (int idx = tid; idx < 32 * 40; idx += 256) {
            int k = idx / 40, c = idx % 40;
            Ws[k * W2S_STRIDE + c] = f2tf32(W[(size_t)(kc * 32 + k) * 40 + c]);
        }
        __syncthreads();
#pragma unroll
        for (int kk = 0; kk < 4; ++kk) {
            const int k8 = kk * 8;
            const int rbase = warp * 16;
            unsigned int a0 = Xs[(rbase + grp) * XS_STRIDE + k8 + qid];
            unsigned int a1 = Xs[(rbase + grp + 8) * XS_STRIDE + k8 + qid];
            unsigned int a2 = Xs[(rbase + grp) * XS_STRIDE + k8 + qid + 4];
            unsigned int a3 = Xs[(rbase + grp + 8) * XS_STRIDE + k8 + qid + 4];
#pragma unroll
            for (int nt = 0; nt < 5; ++nt) {
                unsigned int b0 = Ws[(k8 + qid) * W2S_STRIDE + nt * 8 + grp];
                unsigned int b1 = Ws[(k8 + qid + 4) * W2S_STRIDE + nt * 8 + grp];
                asm volatile(
                    "mma.sync.aligned.m16n8k8.row.col.f32.tf32.tf32.f32 "
                    "{%0,%1,%2,%3}, {%4,%5,%6,%7}, {%8,%9}, {%0,%1,%2,%3};"
                    : "+f"(acc[nt][0]), "+f"(acc[nt][1]), "+f"(acc[nt][2]), "+f"(acc[nt][3])
                    : "r"(a0), "r"(a1), "r"(a2), "r"(a3), "r"(b0), "r"(b1));
            }
        }
    }
    int r0 = n0 + warp * 16 + grp;
    int r1 = r0 + 8;
    float d0 = (r0 < n) ? g_dinv[r0] : 0.f;
    float d1 = (r1 < n) ? g_dinv[r1] : 0.f;
#pragma unroll
    for (int nt = 0; nt < 5; ++nt) {
        int col = nt * 8 + 2 * qid;
        if (r0 < n) {
            __half2 h = __float22half2_rn(make_float2(acc[nt][0] * d0, acc[nt][1] * d0));
            *(__half2*)(g_ph + (size_t)r0 * 40 + col) = h;
        }
        if (r1 < n) {
            __half2 h = __float22half2_rn(make_float2(acc[nt][2] * d1, acc[nt][3] * d1));
            *(__half2*)(g_ph + (size_t)r1 * 40 + col) = h;
        }
    }
}

// ---------------- aggregation ----------------
__device__ __forceinline__ float4 cvt4(uint2 r) {
    float2 a = __half22float2(*(const __half2*)&r.x);
    float2 b = __half22float2(*(const __half2*)&r.y);
    return make_float4(a.x, a.y, b.x, b.y);
}

// layer 1: unscaled fp16 messages; dinv[src] folded at gather.
__global__ void k_agg128(const float* __restrict__ bias, float* __restrict__ out, int n) {
    int warp = (blockIdx.x * blockDim.x + threadIdx.x) >> 5;
    if (warp >= n) return;
    int lane = threadIdx.x & 31;
    const uint2* p = (const uint2*)g_ph;
    float diw = g_dinv[warp];
    float4 self = cvt4(p[(size_t)warp * 32 + lane]);
    float4 acc;
    acc.x = self.x * diw; acc.y = self.y * diw;
    acc.z = self.z * diw; acc.w = self.w * diw;
    int j = g_rowptr[warp];
    int end = g_rowptr[warp + 1];
    for (; j < end && (j & 3); ++j) {
        int s = g_csrsrc[j];
        float d = g_dinv[s];
        float4 v = cvt4(__ldg(&p[(size_t)s * 32 + lane]));
        acc.x = fmaf(v.x, d, acc.x); acc.y = fmaf(v.y, d, acc.y);
        acc.z = fmaf(v.z, d, acc.z); acc.w = fmaf(v.w, d, acc.w);
    }
    for (; j + 4 <= end; j += 4) {
        int4 s4 = __ldg((const int4*)&g_csrsrc[j]);
        float d0 = g_dinv[s4.x], d1 = g_dinv[s4.y], d2 = g_dinv[s4.z], d3 = g_dinv[s4.w];
        float4 v0 = cvt4(__ldg(&p[(size_t)s4.x * 32 + lane]));
        float4 v1 = cvt4(__ldg(&p[(size_t)s4.y * 32 + lane]));
        float4 v2 = cvt4(__ldg(&p[(size_t)s4.z * 32 + lane]));
        float4 v3 = cvt4(__ldg(&p[(size_t)s4.w * 32 + lane]));
        acc.x = fmaf(v0.x, d0, fmaf(v1.x, d1, fmaf(v2.x, d2, fmaf(v3.x, d3, acc.x))));
        acc.y = fmaf(v0.y, d0, fmaf(v1.y, d1, fmaf(v2.y, d2, fmaf(v3.y, d3, acc.y))));
        acc.z = fmaf(v0.z, d0, fmaf(v1.z, d1, fmaf(v2.z, d2, fmaf(v3.z, d3, acc.z))));
        acc.w = fmaf(v0.w, d0, fmaf(v1.w, d1, fmaf(v2.w, d2, fmaf(v3.w, d3, acc.w))));
    }
    for (; j < end; ++j) {
        int s = g_csrsrc[j];
        float d = g_dinv[s];
        float4 v = cvt4(__ldg(&p[(size_t)s * 32 + lane]));
        acc.x = fmaf(v.x, d, acc.x); acc.y = fmaf(v.y, d, acc.y);
        acc.z = fmaf(v.z, d, acc.z); acc.w = fmaf(v.w, d, acc.w);
    }
    float4 bb = ((const float4*)bias)[lane];
    float4 o;
    o.x = fmaxf(fmaf(acc.x, diw, bb.x), 0.f);
    o.y = fmaxf(fmaf(acc.y, diw, bb.y), 0.f);
    o.z = fmaxf(fmaf(acc.z, diw, bb.z), 0.f);
    o.w = fmaxf(fmaf(acc.w, diw, bb.w), 0.f);
    ((float4*)out)[(size_t)warp * 32 + lane] = o;
}

// layer 2: messages pre-scaled by dinv in gemm epilogue.
__global__ void k_agg40(const float* __restrict__ bias, float* __restrict__ out, int n) {
    int warp = (blockIdx.x * blockDim.x + threadIdx.x) >> 5;
    if (warp >= n) return;
    int lane = threadIdx.x & 31;
    bool act = lane < 20;
    const unsigned int* p = (const unsigned int*)g_ph;
    float diw = g_dinv[warp];
    float2 acc = make_float2(0.f, 0.f);
    if (act) acc = __half22float2(*(const __half2*)&p[(size_t)warp * 20 + lane]);
    int j = g_rowptr[warp];
    int end = g_rowptr[warp + 1];
    for (; j < end && (j & 3); ++j) {
        int s = g_csrsrc[j];
        if (act) {
            unsigned int r = __ldg(&p[(size_t)s * 20 + lane]);
            float2 v = __half22float2(*(const __half2*)&r);
            acc.x += v.x; acc.y += v.y;
        }
    }
    for (; j + 4 <= end; j += 4) {
        int4 s4 = __ldg((const int4*)&g_csrsrc[j]);
        if (act) {
            unsigned int r0 = __ldg(&p[(size_t)s4.x * 20 + lane]);
            unsigned int r1 = __ldg(&p[(size_t)s4.y * 20 + lane]);
            unsigned int r2 = __ldg(&p[(size_t)s4.z * 20 + lane]);
            unsigned int r3 = __ldg(&p[(size_t)s4.w * 20 + lane]);
            float2 v0 = __half22float2(*(const __half2*)&r0);
            float2 v1 = __half22float2(*(const __half2*)&r1);
            float2 v2 = __half22float2(*(const __half2*)&r2);
            float2 v3 = __half22float2(*(const __half2*)&r3);
            acc.x += (v0.x + v1.x) + (v2.x + v3.x);
            acc.y += (v0.y + v1.y) + (v2.y + v3.y);
        }
    }
    for (; j < end; ++j) {
        int s = g_csrsrc[j];
        if (act) {
            unsigned int r = __ldg(&p[(size_t)s * 20 + lane]);
            float2 v = __half22float2(*(const __half2*)&r);
            acc.x += v.x; acc.y += v.y;
        }
    }
    if (act) {
        float2 bb = ((const float2*)bias)[lane];
        float2 o;
        o.x = fmaf(acc.x, diw, bb.x);
        o.y = fmaf(acc.y, diw, bb.y);
        ((float2*)out)[(size_t)warp * 20 + lane] = o;
    }
}

// ---------------- launch ----------------
extern "C" void kernel_launch(void* const* d_in, const int* in_sizes, int n_in,
                              void* d_out, int out_size) {
    const float* x  = (const float*)d_in[0];
    const void*  ei = d_in[1];
    const float* W1 = (const float*)d_in[2];
    const float* b1 = (const float*)d_in[3];
    const float* W2 = (const float*)d_in[4];
    const float* b2 = (const float*)d_in[5];

    int n = in_sizes[0] / 128;
    int E = in_sizes[1] / 2;

    float* out    = (float*)d_out;
    float* logits = out;                       // [n, 40]
    float* hidden;
    if ((size_t)out_size >= (size_t)n * (40 + 128)) {
        hidden = out + (size_t)n * 40;         // [n, 128]
    } else {
        cudaGetSymbolAddress((void**)&hidden, g_hidden_scratch);
    }

    int nb_tc = (n + 127) / 128;
    int nb_e2 = (E / 2 + 255) / 256 + 1;
    int nb_scan = (n + 1023) / 1024;
    int nb_warp = (n + 7) / 8;

    cudaStream_t s2;
    cudaEvent_t evFork, evGemm;
    cudaStreamCreateWithFlags(&s2, cudaStreamNonBlocking);
    cudaEventCreateWithFlags(&evFork, cudaEventDisableTiming);
    cudaEventCreateWithFlags(&evGemm, cudaEventDisableTiming);

    // side stream: tensor-core GEMM1 (fp16 messages, unscaled)
    cudaEventRecord(evFork, 0);
    cudaStreamWaitEvent(s2, evFork, 0);
    k_gemm_tc<<<nb_tc, 256, 0, s2>>>(x, W1, n);
    cudaEventRecord(evGemm, s2);

    // main stream: CSR chain (self-cleaning, 2 edges/thread)
    k_deg_count<<<nb_e2, 256>>>(ei, E, n);
    k_scan     <<<nb_scan, 256>>>(n, E);
    k_scatter  <<<nb_e2, 256>>>(ei, E, n);

    // join, then serial tail
    cudaStreamWaitEvent(0, evGemm, 0);
    k_agg128   <<<nb_warp, 256>>>(b1, hidden, n);
    k_gemm40_tc<<<nb_tc, 256>>>(hidden, W2, n);
    k_agg40    <<<nb_warp, 256>>>(b2, logits, n);

    cudaEventDestroy(evFork);
    cudaEventDestroy(evGemm);
    cudaStreamDestroy(s2);
}